// round 10
// baseline (speedup 1.0000x reference)
#include <cuda_runtime.h>
#include <cuda_fp16.h>
#include <cstdint>

// Problem constants (fixed by the reference)
#define NN    100000      // nodes
#define DIN   512
#define DOUT  512
#define EMAX  3200000     // edges

// Scratch (device globals per harness alloc rules)
__device__ __half g_suph[(size_t)NN * DOUT];       // 100 MB, support in fp16 (fits L2)
__device__ __half g_Ah[(size_t)NN * DIN];          // 100 MB, A in fp16
__device__ __half g_Bth[DIN * DOUT];               // 0.5 MB, W^T in fp16 (n-major)
__device__ int    g_counts [NN];
__device__ int    g_offsets[NN + 1];
__device__ int    g_cursor [NN];
__device__ int    g_blocksums[128];
__device__ uint2  g_epack[EMAX];                   // packed (col, val-bits) per CSR slot
__device__ int    g_idx_is64;

#define SCAN_ELEMS 1024
#define SCAN_NB   ((NN + SCAN_ELEMS - 1) / SCAN_ELEMS)   // 98

// ---------------------------------------------------------------------------
// Kernel: detect index dtype (int64 vs int32-packed).
// ---------------------------------------------------------------------------
__global__ void detect_idx_kernel(const long long* __restrict__ rows, int n_edges)
{
    __shared__ int bad;
    if (threadIdx.x == 0) bad = 0;
    __syncthreads();
    int limit = 2048;
    if (limit > n_edges / 2) limit = n_edges / 2;
    for (int i = threadIdx.x; i < limit; i += blockDim.x) {
        long long v = rows[i];
        if (v < 0 || v >= NN) bad = 1;
    }
    __syncthreads();
    if (threadIdx.x == 0) g_idx_is64 = bad ? 0 : 1;
}

__device__ __forceinline__ long long load_idx(const void* p, int e)
{
    if (g_idx_is64) return ((const long long*)p)[e];
    return (long long)((const int*)p)[e];
}

// ---------------------------------------------------------------------------
// Convert A fp32 -> fp16 (streaming).
// ---------------------------------------------------------------------------
__global__ __launch_bounds__(256)
void convert_a_kernel(const float4* __restrict__ in, __half2* __restrict__ out,
                      long long n4)
{
    long long i = (long long)blockIdx.x * blockDim.x + threadIdx.x;
    long long stride = (long long)gridDim.x * blockDim.x;
    for (; i < n4; i += stride) {
        float4 v = in[i];
        out[i * 2 + 0] = __floats2half2_rn(v.x, v.y);
        out[i * 2 + 1] = __floats2half2_rn(v.z, v.w);
    }
}

// ---------------------------------------------------------------------------
// Convert + transpose W: Bth[n][k] = (half)W[k][n].
// ---------------------------------------------------------------------------
__global__ void convert_w_kernel(const float* __restrict__ W, __half* __restrict__ Bth)
{
    __shared__ float tile[32][33];
    int bx = blockIdx.x * 32, by = blockIdx.y * 32;
    int tx = threadIdx.x, ty = threadIdx.y;
#pragma unroll
    for (int i = 0; i < 32; i += 8)
        tile[ty + i][tx] = W[(by + ty + i) * DOUT + bx + tx];
    __syncthreads();
#pragma unroll
    for (int i = 0; i < 32; i += 8)
        Bth[(long long)(bx + ty + i) * DIN + by + tx] = __float2half_rn(tile[tx][ty + i]);
}

// ---------------------------------------------------------------------------
// FP16 tensor-core GEMM, fp32 accum, fp16 OUTPUT. BM=BN=128.
// R10: BK=32 chunks, 3-stage cp.async ring -> 2 chunks always in flight.
// ---------------------------------------------------------------------------
#define SW 20                                   // words per tile row (16 data + 4 pad)
#define STG_WORDS (128 * SW)                    // 2560 words = 10240 B per operand/stage
#define G_SMEM_WORDS (6 * STG_WORDS)            // 3 stages x 2 operands = 61440 B

__device__ __forceinline__ void cp_async16(uint32_t saddr, const void* gptr, int src_bytes)
{
    asm volatile("cp.async.cg.shared.global [%0], [%1], 16, %2;\n"
                 :: "r"(saddr), "l"(gptr), "r"(src_bytes));
}

__device__ __forceinline__ void ldsm_x4(uint32_t& r0, uint32_t& r1,
                                        uint32_t& r2, uint32_t& r3, uint32_t addr)
{
    asm volatile("ldmatrix.sync.aligned.m8n8.x4.shared.b16 {%0,%1,%2,%3}, [%4];"
                 : "=r"(r0), "=r"(r1), "=r"(r2), "=r"(r3) : "r"(addr));
}

__global__ __launch_bounds__(256, 2)
void gemm_fp16_kernel(const __half* __restrict__ A, const __half* __restrict__ Bt,
                      __half* __restrict__ C, int M)
{
    extern __shared__ uint32_t smem[];
    const int tid  = threadIdx.x;
    const int wid  = tid >> 5;
    const int lane = tid & 31;
    const int gid  = lane >> 2;
    const int tg   = lane & 3;

    const int blockRow = blockIdx.y * 128;
    const int blockCol = blockIdx.x * 128;

    uint32_t smem_base;
    asm("{ .reg .u64 t; cvta.to.shared.u64 t, %1; cvt.u32.u64 %0, t; }"
        : "=r"(smem_base) : "l"(smem));

    const int warpM = (wid & 1) * 64;
    const int warpN = (wid >> 1) * 32;

    // ldmatrix lane geometry
    const int lb = lane >> 3;
    const int lr = lane & 7;
    const int a_lane_off = ((lb & 1) * 8 + lr) * SW + (lb >> 1) * 4;   // words
    const int b_lane_row = (lb >> 1) * 8 + lr;
    const int b_lane_w   = (lb & 1) * 4;

    // loader mapping: 2 x 16B per operand per chunk per thread
    const int ldRow = tid >> 1;            // 0..127
    const int ldSeg = (tid & 1) * 2;       // segment base (16B units within 64B row)

    float acc[4][4][4];
#pragma unroll
    for (int i = 0; i < 4; i++)
#pragma unroll
        for (int j = 0; j < 4; j++)
#pragma unroll
            for (int t = 0; t < 4; t++) acc[i][j][t] = 0.f;

    const long long aRow = (long long)blockRow + ldRow;
    const bool aOk = aRow < M;
    const __half* aSrc = A + (aOk ? aRow : 0) * DIN;
    const __half* bSrc = Bt + (long long)(blockCol + ldRow) * DIN;

    auto issue_chunk = [&](int chunk) {
        const int st = chunk % 3;
        const int kElem = chunk * 32 + ldSeg * 8;          // 16B = 8 halves
        const uint32_t aBuf = smem_base + (st * 2 * STG_WORDS) * 4;
        const uint32_t bBuf = aBuf + STG_WORDS * 4;
#pragma unroll
        for (int s2 = 0; s2 < 2; s2++) {
            uint32_t off = (ldRow * SW + (ldSeg + s2) * 4) * 4;
            cp_async16(aBuf + off, aSrc + kElem + s2 * 8, aOk ? 16 : 0);
            cp_async16(bBuf + off, bSrc + kElem + s2 * 8, 16);
        }
        asm volatile("cp.async.commit_group;");
    };

    const int NCHUNK = DIN / 32;   // 16
    issue_chunk(0);
    issue_chunk(1);
    issue_chunk(2);

    for (int c = 0; c < NCHUNK; c++) {
        // wait for group c: pending after issues = min(3, NCHUNK-c)
        if (c <= NCHUNK - 3)      asm volatile("cp.async.wait_group 2;");
        else if (c == NCHUNK - 2) asm volatile("cp.async.wait_group 1;");
        else                      asm volatile("cp.async.wait_group 0;");
        __syncthreads();

        const int st = c % 3;
        const uint32_t aBase = smem_base + (st * 2 * STG_WORDS) * 4;
        const uint32_t bBase = aBase + STG_WORDS * 4;

#pragma unroll
        for (int s = 0; s < 2; s++) {          // 2 k-steps of 16
            const int kw = s * 8;
            uint32_t afr[4][4], bfr[4][2];
#pragma unroll
            for (int i = 0; i < 4; i++) {
                uint32_t addr = aBase + ((warpM + i * 16) * SW + kw + a_lane_off) * 4;
                ldsm_x4(afr[i][0], afr[i][1], afr[i][2], afr[i][3], addr);
            }
#pragma unroll
            for (int jj = 0; jj < 2; jj++) {
                const int j0 = jj * 2;
                uint32_t addr = bBase +
                    ((warpN + j0 * 8 + b_lane_row) * SW + kw + b_lane_w) * 4;
                ldsm_x4(bfr[j0][0], bfr[j0][1], bfr[j0 + 1][0], bfr[j0 + 1][1], addr);
            }
#pragma unroll
            for (int i = 0; i < 4; i++)
#pragma unroll
                for (int j = 0; j < 4; j++) {
                    asm volatile(
                        "mma.sync.aligned.m16n8k16.row.col.f32.f16.f16.f32 "
                        "{%0,%1,%2,%3}, {%4,%5,%6,%7}, {%8,%9}, {%0,%1,%2,%3};"
                        : "+f"(acc[i][j][0]), "+f"(acc[i][j][1]),
                          "+f"(acc[i][j][2]), "+f"(acc[i][j][3])
                        : "r"(afr[i][0]), "r"(afr[i][1]), "r"(afr[i][2]), "r"(afr[i][3]),
                          "r"(bfr[j][0]), "r"(bfr[j][1]));
                }
        }
        __syncthreads();
        if (c + 3 < NCHUNK) issue_chunk(c + 3);
    }

    // Epilogue: fp16 output
#pragma unroll
    for (int i = 0; i < 4; i++) {
        long long row0 = (long long)blockRow + warpM + i * 16 + gid;
#pragma unroll
        for (int j = 0; j < 4; j++) {
            int col = blockCol + warpN + j * 8 + tg * 2;
            if (row0 < M)
                *(__half2*)(C + row0 * DOUT + col) =
                    __floats2half2_rn(acc[i][j][0], acc[i][j][1]);
            if (row0 + 8 < M)
                *(__half2*)(C + (row0 + 8) * DOUT + col) =
                    __floats2half2_rn(acc[i][j][2], acc[i][j][3]);
        }
    }
}

// ---------------------------------------------------------------------------
// CSR build
// ---------------------------------------------------------------------------
__global__ __launch_bounds__(128)
void hist_kernel(const void* __restrict__ rows, int E)
{
    int stride = gridDim.x * blockDim.x;
    for (int e = blockIdx.x * blockDim.x + threadIdx.x; e < E; e += stride) {
        int r = (int)load_idx(rows, e);
        atomicAdd(&g_counts[r], 1);
    }
}

__global__ __launch_bounds__(256)
void scan_blocksum_kernel()
{
    __shared__ int sh[256];
    int b = blockIdx.x, t = threadIdx.x;
    int base = b * SCAN_ELEMS + t * 4;
    int s = 0;
#pragma unroll
    for (int i = 0; i < 4; i++) {
        int idx = base + i;
        if (idx < NN) s += g_counts[idx];
    }
    sh[t] = s; __syncthreads();
    for (int off = 128; off > 0; off >>= 1) {
        if (t < off) sh[t] += sh[t + off];
        __syncthreads();
    }
    if (t == 0) g_blocksums[b] = sh[0];
}

__global__ void scan_top_kernel(int E)
{
    if (threadIdx.x == 0) {
        int run = 0;
        for (int i = 0; i < SCAN_NB; i++) {
            int v = g_blocksums[i];
            g_blocksums[i] = run;
            run += v;
        }
        g_offsets[NN] = E;
    }
}

__global__ __launch_bounds__(256)
void scan_write_kernel()
{
    __shared__ int sh[256];
    int b = blockIdx.x, t = threadIdx.x;
    int base = b * SCAN_ELEMS + t * 4;
    int v[4];
#pragma unroll
    for (int i = 0; i < 4; i++)
        v[i] = (base + i < NN) ? g_counts[base + i] : 0;
    int s = v[0] + v[1] + v[2] + v[3];
    sh[t] = s; __syncthreads();
    for (int off = 1; off < 256; off <<= 1) {
        int x = (t >= off) ? sh[t - off] : 0;
        __syncthreads();
        sh[t] += x;
        __syncthreads();
    }
    int excl = sh[t] - s + g_blocksums[b];
#pragma unroll
    for (int i = 0; i < 4; i++) {
        int idx = base + i;
        if (idx < NN) {
            g_offsets[idx] = excl;
            g_cursor[idx]  = excl;
        }
        excl += v[i];
    }
}

// Packed (col, val) single 8B store per edge.
__global__ __launch_bounds__(128)
void bucket_kernel(const void* __restrict__ rows, const void* __restrict__ cols,
                   const float* __restrict__ vals, int E)
{
    int stride = gridDim.x * blockDim.x;
    for (int e = blockIdx.x * blockDim.x + threadIdx.x; e < E; e += stride) {
        int r = (int)load_idx(rows, e);
        int c = (int)load_idx(cols, e);
        int pos = atomicAdd(&g_cursor[r], 1);
        g_epack[pos] = make_uint2((unsigned)c, __float_as_uint(vals[e]));
    }
}

// ---------------------------------------------------------------------------
// Aggregation over fp16 support: block per node, fp32 accum, fused ReLU.
// ---------------------------------------------------------------------------
__global__ __launch_bounds__(128)
void aggregate_kernel(const __half* __restrict__ sup, float* __restrict__ out)
{
    const int node = blockIdx.x;
    const int t = threadIdx.x;
    const int beg = g_offsets[node];
    const int end = g_offsets[node + 1];

    __shared__ int   sc[128];
    __shared__ float sv[128];

    float4 acc = make_float4(0.f, 0.f, 0.f, 0.f);

    for (int j0 = beg; j0 < end; j0 += 128) {
        int m = end - j0; if (m > 128) m = 128;
        if (t < m) {
            uint2 p = g_epack[j0 + t];
            sc[t] = (int)p.x;
            sv[t] = __uint_as_float(p.y);
        }
        __syncthreads();

        int k = 0;
        for (; k + 4 <= m; k += 4) {
            const uint2* p0 = (const uint2*)(sup + (long long)sc[k + 0] * DOUT) + t;
            const uint2* p1 = (const uint2*)(sup + (long long)sc[k + 1] * DOUT) + t;
            const uint2* p2 = (const uint2*)(sup + (long long)sc[k + 2] * DOUT) + t;
            const uint2* p3 = (const uint2*)(sup + (long long)sc[k + 3] * DOUT) + t;
            uint2 u0 = __ldg(p0), u1 = __ldg(p1), u2 = __ldg(p2), u3 = __ldg(p3);
            float v0 = sv[k + 0], v1 = sv[k + 1], v2 = sv[k + 2], v3 = sv[k + 3];

            float2 a0 = __half22float2(*(__half2*)&u0.x), b0 = __half22float2(*(__half2*)&u0.y);
            float2 a1 = __half22float2(*(__half2*)&u1.x), b1 = __half22float2(*(__half2*)&u1.y);
            float2 a2 = __half22float2(*(__half2*)&u2.x), b2 = __half22float2(*(__half2*)&u2.y);
            float2 a3 = __half22float2(*(__half2*)&u3.x), b3 = __half22float2(*(__half2*)&u3.y);

            acc.x += v0 * a0.x; acc.y += v0 * a0.y; acc.z += v0 * b0.x; acc.w += v0 * b0.y;
            acc.x += v1 * a1.x; acc.y += v1 * a1.y; acc.z += v1 * b1.x; acc.w += v1 * b1.y;
            acc.x += v2 * a2.x; acc.y += v2 * a2.y; acc.z += v2 * b2.x; acc.w += v2 * b2.y;
            acc.x += v3 * a3.x; acc.y += v3 * a3.y; acc.z += v3 * b3.x; acc.w += v3 * b3.y;
        }
        for (; k < m; k++) {
            uint2 u = __ldg((const uint2*)(sup + (long long)sc[k] * DOUT) + t);
            float v = sv[k];
            float2 a = __half22float2(*(__half2*)&u.x), b = __half22float2(*(__half2*)&u.y);
            acc.x += v * a.x; acc.y += v * a.y; acc.z += v * b.x; acc.w += v * b.y;
        }
        __syncthreads();
    }

    acc.x = fmaxf(acc.x, 0.f); acc.y = fmaxf(acc.y, 0.f);
    acc.z = fmaxf(acc.z, 0.f); acc.w = fmaxf(acc.w, 0.f);
    ((float4*)out)[(long long)node * (DOUT / 4) + t] = acc;
}

// ---------------------------------------------------------------------------
// kernel_launch
// ---------------------------------------------------------------------------
extern "C" void kernel_launch(void* const* d_in, const int* in_sizes, int n_in,
                              void* d_out, int out_size)
{
    const float* features = (const float*)d_in[0];
    const float* weight   = (const float*)d_in[1];
    const void*  rows     = d_in[2];
    const void*  cols     = d_in[3];
    const float* vals     = (const float*)d_in[4];
    float* out = (float*)d_out;

    const int M = in_sizes[0] / DIN;   // 100000
    const int E = in_sizes[4];         // 3200000

    __half* suph = nullptr;
    cudaGetSymbolAddress((void**)&suph, g_suph);
    __half* ah = nullptr;
    cudaGetSymbolAddress((void**)&ah, g_Ah);
    __half* bth = nullptr;
    cudaGetSymbolAddress((void**)&bth, g_Bth);
    int* counts_ptr = nullptr;
    cudaGetSymbolAddress((void**)&counts_ptr, g_counts);

    static bool init_done = false;
    static cudaStream_t s1;
    static cudaEvent_t ev_fork, ev_join;
    if (!init_done) {
        cudaFuncSetAttribute(gemm_fp16_kernel,
                             cudaFuncAttributeMaxDynamicSharedMemorySize,
                             G_SMEM_WORDS * 4);
        cudaStreamCreateWithFlags(&s1, cudaStreamNonBlocking);
        cudaEventCreateWithFlags(&ev_fork, cudaEventDisableTiming);
        cudaEventCreateWithFlags(&ev_join, cudaEventDisableTiming);
        init_done = true;
    }

    // ---- fork ----
    cudaEventRecord(ev_fork, 0);
    cudaStreamWaitEvent(s1, ev_fork, 0);

    // Branch B (side stream): CSR build
    cudaMemsetAsync(counts_ptr, 0, (size_t)NN * sizeof(int), s1);
    detect_idx_kernel<<<1, 256, 0, s1>>>((const long long*)rows, E);
    hist_kernel<<<4096, 128, 0, s1>>>(rows, E);
    scan_blocksum_kernel<<<SCAN_NB, 256, 0, s1>>>();
    scan_top_kernel<<<1, 32, 0, s1>>>(E);
    scan_write_kernel<<<SCAN_NB, 256, 0, s1>>>();
    bucket_kernel<<<4096, 128, 0, s1>>>(rows, cols, vals, E);
    cudaEventRecord(ev_join, s1);

    // Branch A (capture stream): fp32->fp16 converts, then fp16 GEMM
    const long long a4 = (long long)M * DIN / 4;
    convert_a_kernel<<<2048, 256>>>((const float4*)features, (__half2*)ah, a4);
    convert_w_kernel<<<dim3(DOUT / 32, DIN / 32), dim3(32, 8)>>>(weight, bth);
    dim3 gemm_grid(DOUT / 128, (M + 127) / 128);
    gemm_fp16_kernel<<<gemm_grid, 256, G_SMEM_WORDS * 4>>>(ah, bth, suph, M);

    // ---- join ----
    cudaStreamWaitEvent(0, ev_join, 0);

    // Aggregation over fp16 support + fused ReLU
    aggregate_kernel<<<M, 128>>>(suph, out);
}

// round 11
// speedup vs baseline: 1.0696x; 1.0696x over previous
#include <cuda_runtime.h>
#include <cuda_fp16.h>
#include <cstdint>

// Problem constants (fixed by the reference)
#define NN    100000      // nodes
#define DIN   512
#define DOUT  512
#define EMAX  3200000     // edges

// Scratch (device globals per harness alloc rules)
__device__ __half g_suph[(size_t)NN * DOUT];       // 100 MB, support in fp16 (fits L2)
__device__ __half g_Ah[(size_t)NN * DIN];          // 100 MB, A in fp16
__device__ __half g_Bth[DIN * DOUT];               // 0.5 MB, W^T in fp16 (n-major)
__device__ int    g_counts [NN];
__device__ int    g_offsets[NN + 1];
__device__ int    g_cursor [NN];
__device__ int    g_blocksums[128];
__device__ int    g_scan_ready;
__device__ uint2  g_epack[EMAX];                   // packed (col, val-bits) per CSR slot
__device__ int    g_idx_is64;

#define SCAN_ELEMS 1024
#define SCAN_NB   ((NN + SCAN_ELEMS - 1) / SCAN_ELEMS)   // 98 (< 148 SMs: co-resident)

// ---------------------------------------------------------------------------
// Kernel: detect index dtype (int64 vs int32-packed). Also zeroes scan flag.
// ---------------------------------------------------------------------------
__global__ void detect_idx_kernel(const long long* __restrict__ rows, int n_edges)
{
    __shared__ int bad;
    if (threadIdx.x == 0) { bad = 0; g_scan_ready = 0; }
    __syncthreads();
    int limit = 2048;
    if (limit > n_edges / 2) limit = n_edges / 2;
    for (int i = threadIdx.x; i < limit; i += blockDim.x) {
        long long v = rows[i];
        if (v < 0 || v >= NN) bad = 1;
    }
    __syncthreads();
    if (threadIdx.x == 0) g_idx_is64 = bad ? 0 : 1;
}

__device__ __forceinline__ long long load_idx(const void* p, int e)
{
    if (g_idx_is64) return ((const long long*)p)[e];
    return (long long)((const int*)p)[e];
}

// ---------------------------------------------------------------------------
// Convert A fp32 -> fp16 (streaming).
// ---------------------------------------------------------------------------
__global__ __launch_bounds__(256)
void convert_a_kernel(const float4* __restrict__ in, __half2* __restrict__ out,
                      long long n4)
{
    long long i = (long long)blockIdx.x * blockDim.x + threadIdx.x;
    long long stride = (long long)gridDim.x * blockDim.x;
    for (; i < n4; i += stride) {
        float4 v = in[i];
        out[i * 2 + 0] = __floats2half2_rn(v.x, v.y);
        out[i * 2 + 1] = __floats2half2_rn(v.z, v.w);
    }
}

// ---------------------------------------------------------------------------
// Convert + transpose W: Bth[n][k] = (half)W[k][n].
// ---------------------------------------------------------------------------
__global__ void convert_w_kernel(const float* __restrict__ W, __half* __restrict__ Bth)
{
    __shared__ float tile[32][33];
    int bx = blockIdx.x * 32, by = blockIdx.y * 32;
    int tx = threadIdx.x, ty = threadIdx.y;
#pragma unroll
    for (int i = 0; i < 32; i += 8)
        tile[ty + i][tx] = W[(by + ty + i) * DOUT + bx + tx];
    __syncthreads();
#pragma unroll
    for (int i = 0; i < 32; i += 8)
        Bth[(long long)(bx + ty + i) * DIN + by + tx] = __float2half_rn(tile[tx][ty + i]);
}

// ---------------------------------------------------------------------------
// FP16 tensor-core GEMM (exact R9 shape: BK=64, 2-stage, ldmatrix).
// ---------------------------------------------------------------------------
#define HS_STRIDE 36
#define H_BUF_WORDS (128 * HS_STRIDE)
#define H_SMEM_WORDS (4 * H_BUF_WORDS)

__device__ __forceinline__ void cp_async16(uint32_t saddr, const void* gptr, int src_bytes)
{
    asm volatile("cp.async.cg.shared.global [%0], [%1], 16, %2;\n"
                 :: "r"(saddr), "l"(gptr), "r"(src_bytes));
}

__device__ __forceinline__ void ldsm_x4(uint32_t& r0, uint32_t& r1,
                                        uint32_t& r2, uint32_t& r3, uint32_t addr)
{
    asm volatile("ldmatrix.sync.aligned.m8n8.x4.shared.b16 {%0,%1,%2,%3}, [%4];"
                 : "=r"(r0), "=r"(r1), "=r"(r2), "=r"(r3) : "r"(addr));
}

__global__ __launch_bounds__(256, 2)
void gemm_fp16_kernel(const __half* __restrict__ A, const __half* __restrict__ Bt,
                      __half* __restrict__ C, int M)
{
    extern __shared__ uint32_t smem[];
    const int tid  = threadIdx.x;
    const int wid  = tid >> 5;
    const int lane = tid & 31;
    const int gid  = lane >> 2;
    const int tg   = lane & 3;

    const int blockRow = blockIdx.y * 128;
    const int blockCol = blockIdx.x * 128;

    const int ldRow = tid >> 3;
    const int ldCol = (tid & 7) * 4;

    uint32_t smem_base;
    asm("{ .reg .u64 t; cvta.to.shared.u64 t, %1; cvt.u32.u64 %0, t; }"
        : "=r"(smem_base) : "l"(smem));

    const int warpM = (wid & 1) * 64;
    const int warpN = (wid >> 1) * 32;

    const int lb = lane >> 3;
    const int lr = lane & 7;
    const int a_lane_off = ((lb & 1) * 8 + lr) * HS_STRIDE + (lb >> 1) * 4;
    const int b_lane_row = (lb >> 1) * 8 + lr;
    const int b_lane_w   = (lb & 1) * 4;

    float acc[4][4][4];
#pragma unroll
    for (int i = 0; i < 4; i++)
#pragma unroll
        for (int j = 0; j < 4; j++)
#pragma unroll
            for (int t = 0; t < 4; t++) acc[i][j][t] = 0.f;

    auto issue_chunk = [&](int chunk, int buf) {
        const int kElem = chunk * 64 + ldCol * 2;
#pragma unroll
        for (int l = 0; l < 4; l++) {
            int r = ldRow + 32 * l;
            long long gRow = (long long)blockRow + r;
            bool ok = gRow < M;
            const __half* src = A + (ok ? gRow : 0) * DIN + kElem;
            uint32_t dst = smem_base + (buf * H_BUF_WORDS + r * HS_STRIDE + ldCol) * 4;
            cp_async16(dst, src, ok ? 16 : 0);
        }
#pragma unroll
        for (int l = 0; l < 4; l++) {
            int n = ldRow + 32 * l;
            const __half* src = Bt + (long long)(blockCol + n) * DIN + kElem;
            uint32_t dst = smem_base +
                ((2 + buf) * H_BUF_WORDS + n * HS_STRIDE + ldCol) * 4;
            cp_async16(dst, src, 16);
        }
        asm volatile("cp.async.commit_group;");
    };

    issue_chunk(0, 0);

    const int NCHUNK = DIN / 64;   // 8
    int buf = 0;
    for (int c = 0; c < NCHUNK; c++) {
        if (c + 1 < NCHUNK) {
            issue_chunk(c + 1, buf ^ 1);
            asm volatile("cp.async.wait_group 1;");
        } else {
            asm volatile("cp.async.wait_group 0;");
        }
        __syncthreads();

        const uint32_t aBase = smem_base + (buf * H_BUF_WORDS) * 4;
        const uint32_t bBase = smem_base + ((2 + buf) * H_BUF_WORDS) * 4;

#pragma unroll
        for (int s = 0; s < 4; s++) {
            const int kw = s * 8;
            uint32_t afr[4][4], bfr[4][2];
#pragma unroll
            for (int i = 0; i < 4; i++) {
                uint32_t addr = aBase +
                    ((warpM + i * 16) * HS_STRIDE + kw + a_lane_off) * 4;
                ldsm_x4(afr[i][0], afr[i][1], afr[i][2], afr[i][3], addr);
            }
#pragma unroll
            for (int jj = 0; jj < 2; jj++) {
                const int j0 = jj * 2;
                uint32_t addr = bBase +
                    ((warpN + j0 * 8 + b_lane_row) * HS_STRIDE + kw + b_lane_w) * 4;
                ldsm_x4(bfr[j0][0], bfr[j0][1], bfr[j0 + 1][0], bfr[j0 + 1][1], addr);
            }
#pragma unroll
            for (int i = 0; i < 4; i++)
#pragma unroll
                for (int j = 0; j < 4; j++) {
                    asm volatile(
                        "mma.sync.aligned.m16n8k16.row.col.f32.f16.f16.f32 "
                        "{%0,%1,%2,%3}, {%4,%5,%6,%7}, {%8,%9}, {%0,%1,%2,%3};"
                        : "+f"(acc[i][j][0]), "+f"(acc[i][j][1]),
                          "+f"(acc[i][j][2]), "+f"(acc[i][j][3])
                        : "r"(afr[i][0]), "r"(afr[i][1]), "r"(afr[i][2]), "r"(afr[i][3]),
                          "r"(bfr[j][0]), "r"(bfr[j][1]));
                }
        }
        __syncthreads();
        buf ^= 1;
    }

#pragma unroll
    for (int i = 0; i < 4; i++) {
        long long row0 = (long long)blockRow + warpM + i * 16 + gid;
#pragma unroll
        for (int j = 0; j < 4; j++) {
            int col = blockCol + warpN + j * 8 + tg * 2;
            if (row0 < M)
                *(__half2*)(C + row0 * DOUT + col) =
                    __floats2half2_rn(acc[i][j][0], acc[i][j][1]);
            if (row0 + 8 < M)
                *(__half2*)(C + (row0 + 8) * DOUT + col) =
                    __floats2half2_rn(acc[i][j][2], acc[i][j][3]);
        }
    }
}

// ---------------------------------------------------------------------------
// CSR build
// ---------------------------------------------------------------------------
__global__ __launch_bounds__(128)
void hist_kernel(const void* __restrict__ rows, int E)
{
    int stride = gridDim.x * blockDim.x;
    for (int e = blockIdx.x * blockDim.x + threadIdx.x; e < E; e += stride) {
        int r = (int)load_idx(rows, e);
        atomicAdd(&g_counts[r], 1);
    }
}

// Fused scan: 98 co-resident blocks; flag-spin grid sync between phases.
__global__ __launch_bounds__(256)
void scan_fused_kernel(int E)
{
    __shared__ int sh[256];
    const int b = blockIdx.x, t = threadIdx.x;
    const int base = b * SCAN_ELEMS + t * 4;

    int v[4];
#pragma unroll
    for (int i = 0; i < 4; i++)
        v[i] = (base + i < NN) ? g_counts[base + i] : 0;
    int s = v[0] + v[1] + v[2] + v[3];
    sh[t] = s; __syncthreads();
    // inclusive scan over 256 thread sums
    for (int off = 1; off < 256; off <<= 1) {
        int x = (t >= off) ? sh[t - off] : 0;
        __syncthreads();
        sh[t] += x;
        __syncthreads();
    }
    const int blockTotal = sh[255];
    const int localExcl  = sh[t] - s;

    // publish block total, grid-wide flag sync (all 98 blocks co-resident)
    if (t == 0) {
        g_blocksums[b] = blockTotal;
        __threadfence();
        atomicAdd(&g_scan_ready, 1);
    }
    if (t == 0) {
        while (atomicAdd(&g_scan_ready, 0) < SCAN_NB) { }
    }
    __syncthreads();

    // prefix of preceding block totals (98 ints, all in L2)
    int blockBase = 0;
    for (int i = t; i < b; i += 256) blockBase += g_blocksums[i];
    sh[t] = blockBase; __syncthreads();
    // reduce the strided partials (only threads < b contributed; b<=97<256)
    for (int off = 128; off > 0; off >>= 1) {
        if (t < off) sh[t] += sh[t + off];
        __syncthreads();
    }
    blockBase = sh[0];
    __syncthreads();

    int excl = localExcl + blockBase;
#pragma unroll
    for (int i = 0; i < 4; i++) {
        int idx = base + i;
        if (idx < NN) {
            g_offsets[idx] = excl;
            g_cursor[idx]  = excl;
        }
        excl += v[i];
    }
    if (b == 0 && t == 0) g_offsets[NN] = E;
}

// Packed (col, val) single 8B store per edge.
__global__ __launch_bounds__(128)
void bucket_kernel(const void* __restrict__ rows, const void* __restrict__ cols,
                   const float* __restrict__ vals, int E)
{
    int stride = gridDim.x * blockDim.x;
    for (int e = blockIdx.x * blockDim.x + threadIdx.x; e < E; e += stride) {
        int r = (int)load_idx(rows, e);
        int c = (int)load_idx(cols, e);
        int pos = atomicAdd(&g_cursor[r], 1);
        g_epack[pos] = make_uint2((unsigned)c, __float_as_uint(vals[e]));
    }
}

// ---------------------------------------------------------------------------
// Aggregation over fp16 support: block per node, fp32 accum, fused ReLU.
// ---------------------------------------------------------------------------
__global__ __launch_bounds__(128)
void aggregate_kernel(const __half* __restrict__ sup, float* __restrict__ out)
{
    const int node = blockIdx.x;
    const int t = threadIdx.x;
    const int beg = g_offsets[node];
    const int end = g_offsets[node + 1];

    __shared__ int   sc[128];
    __shared__ float sv[128];

    float4 acc = make_float4(0.f, 0.f, 0.f, 0.f);

    for (int j0 = beg; j0 < end; j0 += 128) {
        int m = end - j0; if (m > 128) m = 128;
        if (t < m) {
            uint2 p = g_epack[j0 + t];
            sc[t] = (int)p.x;
            sv[t] = __uint_as_float(p.y);
        }
        __syncthreads();

        int k = 0;
        for (; k + 4 <= m; k += 4) {
            const uint2* p0 = (const uint2*)(sup + (long long)sc[k + 0] * DOUT) + t;
            const uint2* p1 = (const uint2*)(sup + (long long)sc[k + 1] * DOUT) + t;
            const uint2* p2 = (const uint2*)(sup + (long long)sc[k + 2] * DOUT) + t;
            const uint2* p3 = (const uint2*)(sup + (long long)sc[k + 3] * DOUT) + t;
            uint2 u0 = __ldg(p0), u1 = __ldg(p1), u2 = __ldg(p2), u3 = __ldg(p3);
            float v0 = sv[k + 0], v1 = sv[k + 1], v2 = sv[k + 2], v3 = sv[k + 3];

            float2 a0 = __half22float2(*(__half2*)&u0.x), b0 = __half22float2(*(__half2*)&u0.y);
            float2 a1 = __half22float2(*(__half2*)&u1.x), b1 = __half22float2(*(__half2*)&u1.y);
            float2 a2 = __half22float2(*(__half2*)&u2.x), b2 = __half22float2(*(__half2*)&u2.y);
            float2 a3 = __half22float2(*(__half2*)&u3.x), b3 = __half22float2(*(__half2*)&u3.y);

            acc.x += v0 * a0.x; acc.y += v0 * a0.y; acc.z += v0 * b0.x; acc.w += v0 * b0.y;
            acc.x += v1 * a1.x; acc.y += v1 * a1.y; acc.z += v1 * b1.x; acc.w += v1 * b1.y;
            acc.x += v2 * a2.x; acc.y += v2 * a2.y; acc.z += v2 * b2.x; acc.w += v2 * b2.y;
            acc.x += v3 * a3.x; acc.y += v3 * a3.y; acc.z += v3 * b3.x; acc.w += v3 * b3.y;
        }
        for (; k < m; k++) {
            uint2 u = __ldg((const uint2*)(sup + (long long)sc[k] * DOUT) + t);
            float v = sv[k];
            float2 a = __half22float2(*(__half2*)&u.x), b = __half22float2(*(__half2*)&u.y);
            acc.x += v * a.x; acc.y += v * a.y; acc.z += v * b.x; acc.w += v * b.y;
        }
        __syncthreads();
    }

    acc.x = fmaxf(acc.x, 0.f); acc.y = fmaxf(acc.y, 0.f);
    acc.z = fmaxf(acc.z, 0.f); acc.w = fmaxf(acc.w, 0.f);
    ((float4*)out)[(long long)node * (DOUT / 4) + t] = acc;
}

// ---------------------------------------------------------------------------
// kernel_launch
// ---------------------------------------------------------------------------
extern "C" void kernel_launch(void* const* d_in, const int* in_sizes, int n_in,
                              void* d_out, int out_size)
{
    const float* features = (const float*)d_in[0];
    const float* weight   = (const float*)d_in[1];
    const void*  rows     = d_in[2];
    const void*  cols     = d_in[3];
    const float* vals     = (const float*)d_in[4];
    float* out = (float*)d_out;

    const int M = in_sizes[0] / DIN;   // 100000
    const int E = in_sizes[4];         // 3200000

    __half* suph = nullptr;
    cudaGetSymbolAddress((void**)&suph, g_suph);
    __half* ah = nullptr;
    cudaGetSymbolAddress((void**)&ah, g_Ah);
    __half* bth = nullptr;
    cudaGetSymbolAddress((void**)&bth, g_Bth);
    int* counts_ptr = nullptr;
    cudaGetSymbolAddress((void**)&counts_ptr, g_counts);

    static bool init_done = false;
    static cudaStream_t s1;
    static cudaEvent_t ev_fork, ev_join;
    if (!init_done) {
        cudaFuncSetAttribute(gemm_fp16_kernel,
                             cudaFuncAttributeMaxDynamicSharedMemorySize,
                             H_SMEM_WORDS * 4);
        cudaStreamCreateWithFlags(&s1, cudaStreamNonBlocking);
        cudaEventCreateWithFlags(&ev_fork, cudaEventDisableTiming);
        cudaEventCreateWithFlags(&ev_join, cudaEventDisableTiming);
        init_done = true;
    }

    // ---- fork ----
    cudaEventRecord(ev_fork, 0);
    cudaStreamWaitEvent(s1, ev_fork, 0);

    // Branch B (side stream): CSR build
    cudaMemsetAsync(counts_ptr, 0, (size_t)NN * sizeof(int), s1);
    detect_idx_kernel<<<1, 256, 0, s1>>>((const long long*)rows, E);
    hist_kernel<<<4096, 128, 0, s1>>>(rows, E);
    scan_fused_kernel<<<SCAN_NB, 256, 0, s1>>>(E);
    bucket_kernel<<<4096, 128, 0, s1>>>(rows, cols, vals, E);
    cudaEventRecord(ev_join, s1);

    // Branch A (capture stream): fp32->fp16 converts, then fp16 GEMM
    const long long a4 = (long long)M * DIN / 4;
    convert_a_kernel<<<2048, 256>>>((const float4*)features, (__half2*)ah, a4);
    convert_w_kernel<<<dim3(DOUT / 32, DIN / 32), dim3(32, 8)>>>(weight, bth);
    dim3 gemm_grid(DOUT / 128, (M + 127) / 128);
    gemm_fp16_kernel<<<gemm_grid, 256, H_SMEM_WORDS * 4>>>(ah, bth, suph, M);

    // ---- join ----
    cudaStreamWaitEvent(0, ev_join, 0);

    // Aggregation over fp16 support + fused ReLU
    aggregate_kernel<<<M, 128>>>(suph, out);
}

// round 12
// speedup vs baseline: 1.2647x; 1.1823x over previous
#include <cuda_runtime.h>
#include <cuda_fp16.h>
#include <cstdint>

// Problem constants (fixed by the reference)
#define NN    100000      // nodes
#define DIN   512
#define DOUT  512
#define EMAX  3200000     // edges

// Scratch (device globals per harness alloc rules)
__device__ __half g_suph[(size_t)NN * DOUT];       // 100 MB, support in fp16 (fits L2)
__device__ __half g_Ah[(size_t)NN * DIN];          // 100 MB, A in fp16
__device__ __half g_Bth[DIN * DOUT];               // 0.5 MB, W^T in fp16 (n-major)
__device__ int    g_counts [NN];
__device__ int    g_offsets[NN + 1];
__device__ int    g_cursor [NN];
__device__ int    g_blocksums[128];
__device__ int    g_scan_ready;
__device__ uint2  g_epack[EMAX];                   // packed (col, val-bits) per CSR slot
__device__ int    g_idx_is64;

#define SCAN_ELEMS 1024
#define SCAN_NB   ((NN + SCAN_ELEMS - 1) / SCAN_ELEMS)   // 98 (< 148 SMs: co-resident)

// ---------------------------------------------------------------------------
// Kernel: detect index dtype (int64 vs int32-packed). Also zeroes scan flag.
// ---------------------------------------------------------------------------
__global__ void detect_idx_kernel(const long long* __restrict__ rows, int n_edges)
{
    __shared__ int bad;
    if (threadIdx.x == 0) { bad = 0; g_scan_ready = 0; }
    __syncthreads();
    int limit = 2048;
    if (limit > n_edges / 2) limit = n_edges / 2;
    for (int i = threadIdx.x; i < limit; i += blockDim.x) {
        long long v = rows[i];
        if (v < 0 || v >= NN) bad = 1;
    }
    __syncthreads();
    if (threadIdx.x == 0) g_idx_is64 = bad ? 0 : 1;
}

__device__ __forceinline__ long long load_idx(const void* p, int e)
{
    if (g_idx_is64) return ((const long long*)p)[e];
    return (long long)((const int*)p)[e];
}

// ---------------------------------------------------------------------------
// Convert A fp32 -> fp16 (streaming).
// ---------------------------------------------------------------------------
__global__ __launch_bounds__(256)
void convert_a_kernel(const float4* __restrict__ in, __half2* __restrict__ out,
                      long long n4)
{
    long long i = (long long)blockIdx.x * blockDim.x + threadIdx.x;
    long long stride = (long long)gridDim.x * blockDim.x;
    for (; i < n4; i += stride) {
        float4 v = in[i];
        out[i * 2 + 0] = __floats2half2_rn(v.x, v.y);
        out[i * 2 + 1] = __floats2half2_rn(v.z, v.w);
    }
}

// ---------------------------------------------------------------------------
// Convert + transpose W: Bth[n][k] = (half)W[k][n].
// ---------------------------------------------------------------------------
__global__ void convert_w_kernel(const float* __restrict__ W, __half* __restrict__ Bth)
{
    __shared__ float tile[32][33];
    int bx = blockIdx.x * 32, by = blockIdx.y * 32;
    int tx = threadIdx.x, ty = threadIdx.y;
#pragma unroll
    for (int i = 0; i < 32; i += 8)
        tile[ty + i][tx] = W[(by + ty + i) * DOUT + bx + tx];
    __syncthreads();
#pragma unroll
    for (int i = 0; i < 32; i += 8)
        Bth[(long long)(bx + ty + i) * DIN + by + tx] = __float2half_rn(tile[tx][ty + i]);
}

// ---------------------------------------------------------------------------
// FP16 tensor-core GEMM (R9/R11 shape: BK=64, 2-stage, ldmatrix).
// R12: nOff parameter -> launch per 256-column half for GEMM/agg pipelining.
// ---------------------------------------------------------------------------
#define HS_STRIDE 36
#define H_BUF_WORDS (128 * HS_STRIDE)
#define H_SMEM_WORDS (4 * H_BUF_WORDS)

__device__ __forceinline__ void cp_async16(uint32_t saddr, const void* gptr, int src_bytes)
{
    asm volatile("cp.async.cg.shared.global [%0], [%1], 16, %2;\n"
                 :: "r"(saddr), "l"(gptr), "r"(src_bytes));
}

__device__ __forceinline__ void ldsm_x4(uint32_t& r0, uint32_t& r1,
                                        uint32_t& r2, uint32_t& r3, uint32_t addr)
{
    asm volatile("ldmatrix.sync.aligned.m8n8.x4.shared.b16 {%0,%1,%2,%3}, [%4];"
                 : "=r"(r0), "=r"(r1), "=r"(r2), "=r"(r3) : "r"(addr));
}

__global__ __launch_bounds__(256, 2)
void gemm_fp16_kernel(const __half* __restrict__ A, const __half* __restrict__ Bt,
                      __half* __restrict__ C, int M, int nOff)
{
    extern __shared__ uint32_t smem[];
    const int tid  = threadIdx.x;
    const int wid  = tid >> 5;
    const int lane = tid & 31;
    const int gid  = lane >> 2;
    const int tg   = lane & 3;

    const int blockRow = blockIdx.y * 128;
    const int blockCol = nOff + blockIdx.x * 128;

    const int ldRow = tid >> 3;
    const int ldCol = (tid & 7) * 4;

    uint32_t smem_base;
    asm("{ .reg .u64 t; cvta.to.shared.u64 t, %1; cvt.u32.u64 %0, t; }"
        : "=r"(smem_base) : "l"(smem));

    const int warpM = (wid & 1) * 64;
    const int warpN = (wid >> 1) * 32;

    const int lb = lane >> 3;
    const int lr = lane & 7;
    const int a_lane_off = ((lb & 1) * 8 + lr) * HS_STRIDE + (lb >> 1) * 4;
    const int b_lane_row = (lb >> 1) * 8 + lr;
    const int b_lane_w   = (lb & 1) * 4;

    float acc[4][4][4];
#pragma unroll
    for (int i = 0; i < 4; i++)
#pragma unroll
        for (int j = 0; j < 4; j++)
#pragma unroll
            for (int t = 0; t < 4; t++) acc[i][j][t] = 0.f;

    auto issue_chunk = [&](int chunk, int buf) {
        const int kElem = chunk * 64 + ldCol * 2;
#pragma unroll
        for (int l = 0; l < 4; l++) {
            int r = ldRow + 32 * l;
            long long gRow = (long long)blockRow + r;
            bool ok = gRow < M;
            const __half* src = A + (ok ? gRow : 0) * DIN + kElem;
            uint32_t dst = smem_base + (buf * H_BUF_WORDS + r * HS_STRIDE + ldCol) * 4;
            cp_async16(dst, src, ok ? 16 : 0);
        }
#pragma unroll
        for (int l = 0; l < 4; l++) {
            int n = ldRow + 32 * l;
            const __half* src = Bt + (long long)(blockCol + n) * DIN + kElem;
            uint32_t dst = smem_base +
                ((2 + buf) * H_BUF_WORDS + n * HS_STRIDE + ldCol) * 4;
            cp_async16(dst, src, 16);
        }
        asm volatile("cp.async.commit_group;");
    };

    issue_chunk(0, 0);

    const int NCHUNK = DIN / 64;   // 8
    int buf = 0;
    for (int c = 0; c < NCHUNK; c++) {
        if (c + 1 < NCHUNK) {
            issue_chunk(c + 1, buf ^ 1);
            asm volatile("cp.async.wait_group 1;");
        } else {
            asm volatile("cp.async.wait_group 0;");
        }
        __syncthreads();

        const uint32_t aBase = smem_base + (buf * H_BUF_WORDS) * 4;
        const uint32_t bBase = smem_base + ((2 + buf) * H_BUF_WORDS) * 4;

#pragma unroll
        for (int s = 0; s < 4; s++) {
            const int kw = s * 8;
            uint32_t afr[4][4], bfr[4][2];
#pragma unroll
            for (int i = 0; i < 4; i++) {
                uint32_t addr = aBase +
                    ((warpM + i * 16) * HS_STRIDE + kw + a_lane_off) * 4;
                ldsm_x4(afr[i][0], afr[i][1], afr[i][2], afr[i][3], addr);
            }
#pragma unroll
            for (int jj = 0; jj < 2; jj++) {
                const int j0 = jj * 2;
                uint32_t addr = bBase +
                    ((warpN + j0 * 8 + b_lane_row) * HS_STRIDE + kw + b_lane_w) * 4;
                ldsm_x4(bfr[j0][0], bfr[j0][1], bfr[j0 + 1][0], bfr[j0 + 1][1], addr);
            }
#pragma unroll
            for (int i = 0; i < 4; i++)
#pragma unroll
                for (int j = 0; j < 4; j++) {
                    asm volatile(
                        "mma.sync.aligned.m16n8k16.row.col.f32.f16.f16.f32 "
                        "{%0,%1,%2,%3}, {%4,%5,%6,%7}, {%8,%9}, {%0,%1,%2,%3};"
                        : "+f"(acc[i][j][0]), "+f"(acc[i][j][1]),
                          "+f"(acc[i][j][2]), "+f"(acc[i][j][3])
                        : "r"(afr[i][0]), "r"(afr[i][1]), "r"(afr[i][2]), "r"(afr[i][3]),
                          "r"(bfr[j][0]), "r"(bfr[j][1]));
                }
        }
        __syncthreads();
        buf ^= 1;
    }

#pragma unroll
    for (int i = 0; i < 4; i++) {
        long long row0 = (long long)blockRow + warpM + i * 16 + gid;
#pragma unroll
        for (int j = 0; j < 4; j++) {
            int col = blockCol + warpN + j * 8 + tg * 2;
            if (row0 < M)
                *(__half2*)(C + row0 * DOUT + col) =
                    __floats2half2_rn(acc[i][j][0], acc[i][j][1]);
            if (row0 + 8 < M)
                *(__half2*)(C + (row0 + 8) * DOUT + col) =
                    __floats2half2_rn(acc[i][j][2], acc[i][j][3]);
        }
    }
}

// ---------------------------------------------------------------------------
// CSR build (unchanged R11)
// ---------------------------------------------------------------------------
__global__ __launch_bounds__(128)
void hist_kernel(const void* __restrict__ rows, int E)
{
    int stride = gridDim.x * blockDim.x;
    for (int e = blockIdx.x * blockDim.x + threadIdx.x; e < E; e += stride) {
        int r = (int)load_idx(rows, e);
        atomicAdd(&g_counts[r], 1);
    }
}

__global__ __launch_bounds__(256)
void scan_fused_kernel(int E)
{
    __shared__ int sh[256];
    const int b = blockIdx.x, t = threadIdx.x;
    const int base = b * SCAN_ELEMS + t * 4;

    int v[4];
#pragma unroll
    for (int i = 0; i < 4; i++)
        v[i] = (base + i < NN) ? g_counts[base + i] : 0;
    int s = v[0] + v[1] + v[2] + v[3];
    sh[t] = s; __syncthreads();
    for (int off = 1; off < 256; off <<= 1) {
        int x = (t >= off) ? sh[t - off] : 0;
        __syncthreads();
        sh[t] += x;
        __syncthreads();
    }
    const int blockTotal = sh[255];
    const int localExcl  = sh[t] - s;

    if (t == 0) {
        g_blocksums[b] = blockTotal;
        __threadfence();
        atomicAdd(&g_scan_ready, 1);
        while (atomicAdd(&g_scan_ready, 0) < SCAN_NB) { }
    }
    __syncthreads();

    int blockBase = 0;
    for (int i = t; i < b; i += 256) blockBase += g_blocksums[i];
    sh[t] = blockBase; __syncthreads();
    for (int off = 128; off > 0; off >>= 1) {
        if (t < off) sh[t] += sh[t + off];
        __syncthreads();
    }
    blockBase = sh[0];
    __syncthreads();

    int excl = localExcl + blockBase;
#pragma unroll
    for (int i = 0; i < 4; i++) {
        int idx = base + i;
        if (idx < NN) {
            g_offsets[idx] = excl;
            g_cursor[idx]  = excl;
        }
        excl += v[i];
    }
    if (b == 0 && t == 0) g_offsets[NN] = E;
}

__global__ __launch_bounds__(128)
void bucket_kernel(const void* __restrict__ rows, const void* __restrict__ cols,
                   const float* __restrict__ vals, int E)
{
    int stride = gridDim.x * blockDim.x;
    for (int e = blockIdx.x * blockDim.x + threadIdx.x; e < E; e += stride) {
        int r = (int)load_idx(rows, e);
        int c = (int)load_idx(cols, e);
        int pos = atomicAdd(&g_cursor[r], 1);
        g_epack[pos] = make_uint2((unsigned)c, __float_as_uint(vals[e]));
    }
}

// ---------------------------------------------------------------------------
// Aggregation over one 256-column half of support. 64 threads per node:
// each thread owns 4 cols (uint2 gather). fp32 accum, fused ReLU.
// ---------------------------------------------------------------------------
__global__ __launch_bounds__(64)
void aggregate_half_kernel(const __half* __restrict__ sup, float* __restrict__ out,
                           int colOff)
{
    const int node = blockIdx.x;
    const int t = threadIdx.x;
    const int beg = g_offsets[node];
    const int end = g_offsets[node + 1];

    __shared__ int   sc[64];
    __shared__ float sv[64];

    float4 acc = make_float4(0.f, 0.f, 0.f, 0.f);

    for (int j0 = beg; j0 < end; j0 += 64) {
        int m = end - j0; if (m > 64) m = 64;
        if (t < m) {
            uint2 p = g_epack[j0 + t];
            sc[t] = (int)p.x;
            sv[t] = __uint_as_float(p.y);
        }
        __syncthreads();

        int k = 0;
        for (; k + 4 <= m; k += 4) {
            const uint2* p0 = (const uint2*)(sup + (long long)sc[k + 0] * DOUT + colOff) + t;
            const uint2* p1 = (const uint2*)(sup + (long long)sc[k + 1] * DOUT + colOff) + t;
            const uint2* p2 = (const uint2*)(sup + (long long)sc[k + 2] * DOUT + colOff) + t;
            const uint2* p3 = (const uint2*)(sup + (long long)sc[k + 3] * DOUT + colOff) + t;
            uint2 u0 = __ldg(p0), u1 = __ldg(p1), u2 = __ldg(p2), u3 = __ldg(p3);
            float v0 = sv[k + 0], v1 = sv[k + 1], v2 = sv[k + 2], v3 = sv[k + 3];

            float2 a0 = __half22float2(*(__half2*)&u0.x), b0 = __half22float2(*(__half2*)&u0.y);
            float2 a1 = __half22float2(*(__half2*)&u1.x), b1 = __half22float2(*(__half2*)&u1.y);
            float2 a2 = __half22float2(*(__half2*)&u2.x), b2 = __half22float2(*(__half2*)&u2.y);
            float2 a3 = __half22float2(*(__half2*)&u3.x), b3 = __half22float2(*(__half2*)&u3.y);

            acc.x += v0 * a0.x; acc.y += v0 * a0.y; acc.z += v0 * b0.x; acc.w += v0 * b0.y;
            acc.x += v1 * a1.x; acc.y += v1 * a1.y; acc.z += v1 * b1.x; acc.w += v1 * b1.y;
            acc.x += v2 * a2.x; acc.y += v2 * a2.y; acc.z += v2 * b2.x; acc.w += v2 * b2.y;
            acc.x += v3 * a3.x; acc.y += v3 * a3.y; acc.z += v3 * b3.x; acc.w += v3 * b3.y;
        }
        for (; k < m; k++) {
            uint2 u = __ldg((const uint2*)(sup + (long long)sc[k] * DOUT + colOff) + t);
            float v = sv[k];
            float2 a = __half22float2(*(__half2*)&u.x), b = __half22float2(*(__half2*)&u.y);
            acc.x += v * a.x; acc.y += v * a.y; acc.z += v * b.x; acc.w += v * b.y;
        }
        __syncthreads();
    }

    acc.x = fmaxf(acc.x, 0.f); acc.y = fmaxf(acc.y, 0.f);
    acc.z = fmaxf(acc.z, 0.f); acc.w = fmaxf(acc.w, 0.f);
    *((float4*)(out + (long long)node * DOUT + colOff) + t) = acc;
}

// ---------------------------------------------------------------------------
// kernel_launch: converts -> G1 -> (G2 || A1) -> A2, CSR on side stream.
// ---------------------------------------------------------------------------
extern "C" void kernel_launch(void* const* d_in, const int* in_sizes, int n_in,
                              void* d_out, int out_size)
{
    const float* features = (const float*)d_in[0];
    const float* weight   = (const float*)d_in[1];
    const void*  rows     = d_in[2];
    const void*  cols     = d_in[3];
    const float* vals     = (const float*)d_in[4];
    float* out = (float*)d_out;

    const int M = in_sizes[0] / DIN;   // 100000
    const int E = in_sizes[4];         // 3200000

    __half* suph = nullptr;
    cudaGetSymbolAddress((void**)&suph, g_suph);
    __half* ah = nullptr;
    cudaGetSymbolAddress((void**)&ah, g_Ah);
    __half* bth = nullptr;
    cudaGetSymbolAddress((void**)&bth, g_Bth);
    int* counts_ptr = nullptr;
    cudaGetSymbolAddress((void**)&counts_ptr, g_counts);

    static bool init_done = false;
    static cudaStream_t s1, s2;
    static cudaEvent_t ev_fork, ev_csr, ev_g1, ev_a1;
    if (!init_done) {
        cudaFuncSetAttribute(gemm_fp16_kernel,
                             cudaFuncAttributeMaxDynamicSharedMemorySize,
                             H_SMEM_WORDS * 4);
        cudaStreamCreateWithFlags(&s1, cudaStreamNonBlocking);
        cudaStreamCreateWithFlags(&s2, cudaStreamNonBlocking);
        cudaEventCreateWithFlags(&ev_fork, cudaEventDisableTiming);
        cudaEventCreateWithFlags(&ev_csr,  cudaEventDisableTiming);
        cudaEventCreateWithFlags(&ev_g1,   cudaEventDisableTiming);
        cudaEventCreateWithFlags(&ev_a1,   cudaEventDisableTiming);
        init_done = true;
    }

    // ---- fork ----
    cudaEventRecord(ev_fork, 0);
    cudaStreamWaitEvent(s1, ev_fork, 0);

    // Branch B (side stream s1): CSR build
    cudaMemsetAsync(counts_ptr, 0, (size_t)NN * sizeof(int), s1);
    detect_idx_kernel<<<1, 256, 0, s1>>>((const long long*)rows, E);
    hist_kernel<<<4096, 128, 0, s1>>>(rows, E);
    scan_fused_kernel<<<SCAN_NB, 256, 0, s1>>>(E);
    bucket_kernel<<<4096, 128, 0, s1>>>(rows, cols, vals, E);
    cudaEventRecord(ev_csr, s1);

    // Branch A (capture stream s0): converts, then GEMM half 0
    const long long a4 = (long long)M * DIN / 4;
    convert_a_kernel<<<2048, 256>>>((const float4*)features, (__half2*)ah, a4);
    convert_w_kernel<<<dim3(DOUT / 32, DIN / 32), dim3(32, 8)>>>(weight, bth);

    dim3 gemm_grid(2, (M + 127) / 128);            // 2 x 128-col tiles per half
    gemm_fp16_kernel<<<gemm_grid, 256, H_SMEM_WORDS * 4>>>(ah, bth, suph, M, 0);
    cudaEventRecord(ev_g1, 0);

    // s2: aggregation half 0 (needs GEMM half 0 + CSR), overlaps GEMM half 1
    cudaStreamWaitEvent(s2, ev_g1, 0);
    cudaStreamWaitEvent(s2, ev_csr, 0);
    aggregate_half_kernel<<<M, 64, 0, s2>>>(suph, out, 0);
    cudaEventRecord(ev_a1, s2);

    // s0: GEMM half 1, then aggregation half 1
    gemm_fp16_kernel<<<gemm_grid, 256, H_SMEM_WORDS * 4>>>(ah, bth, suph, M, 256);
    cudaStreamWaitEvent(0, ev_csr, 0);
    aggregate_half_kernel<<<M, 64>>>(suph, out, 256);

    // ---- join ----
    cudaStreamWaitEvent(0, ev_a1, 0);
}